// round 14
// baseline (speedup 1.0000x reference)
#include <cuda_runtime.h>
#include <cuda_bf16.h>
#include <math.h>
#include <stdint.h>

#define SQL 48
#define BB  128
#define HDIM 100
#define LDXP 1120   // padded feature width (bf16 rows, 16B-aligned)

typedef unsigned long long ull;

// ------------------------- scratch (device globals; no allocs) -------------
__device__ __nv_bfloat16 g_PX[SQL*BB*LDXP];    // query features (bf16)
__device__ __nv_bfloat16 g_HX[SQL*BB*LDXP];    // support features
__device__ __nv_bfloat16 g_W16[5*400*LDXP];    // all layers' wih in bf16 (zero-padded)
__device__ float g_GP[SQL*BB*400];             // x@wih^T + biases (query)
__device__ float g_GH[SQL*BB*400];             // (support)
__device__ float g_PH[SQL*BB*HDIM];            // hidden states (query, fp32)
__device__ float g_HHs[SQL*BB*HDIM];           // (support)
__device__ float g_feats[500*128];             // pooled features [k][b]
__device__ float g_O1[800*128];                // fc1 activations [o][b]
__device__ float g_Erow[128*2304];             // row-softmax E per batch
__device__ float g_Ecol[128*2304];             // col-softmax E per batch

__constant__ int c_dims[5] = {316, 516, 716, 916, 1116};

// ------------------------- f32x2 helpers -----------------------------------
__device__ __forceinline__ void fma2(ull &d, ull a, ull b) {
    asm("fma.rn.f32x2 %0, %1, %2, %0;" : "+l"(d) : "l"(a), "l"(b));
}
__device__ __forceinline__ ull bcast2(float x) {
    ull r; asm("mov.b64 %0, {%1, %1};" : "=l"(r) : "f"(x)); return r;
}
__device__ __forceinline__ float hsum2(ull a) {
    float2 v = *reinterpret_cast<float2*>(&a); return v.x + v.y;
}

// ------------------- fused prep: wih->bf16 convert + embedding -------------
__global__ __launch_bounds__(128) void prep_kernel(
    const float* __restrict__ W0, const float* __restrict__ W1,
    const float* __restrict__ W2, const float* __restrict__ W3,
    const float* __restrict__ W4,
    const int* __restrict__ q_words, const int* __restrict__ q_chars,
    const int* __restrict__ s_words, const int* __restrict__ s_chars,
    const float* __restrict__ word_emb, const float* __restrict__ char_emb,
    const float* __restrict__ conv_w, const float* __restrict__ conv_b)
{
    int blk = blockIdx.x;
    int tid = threadIdx.x;

    if (blk < 2000) {   // ---- weight conversion path ----
        int layer = blk / 400;
        int row   = blk % 400;
        const float* Wp[5] = {W0, W1, W2, W3, W4};
        const float* W = Wp[layer];
        int d = c_dims[layer];
        __nv_bfloat16* dst = g_W16 + ((size_t)layer*400 + row)*LDXP;
        for (int c = tid; c < LDXP; c += 128) {
            float v = (c < d) ? W[(size_t)row*d + c] : 0.f;
            dst[c] = __float2bfloat16(v);
        }
        return;
    }

    // ---- embedding path ----
    int e = blk - 2000;             // 0..12287
    int which = e / 6144;
    int m = e % 6144;
    const int* words = which ? s_words : q_words;
    const int* chars = which ? s_chars : q_chars;
    __nv_bfloat16* X = which ? g_HX : g_PX;
    int b = m / SQL;
    int s = m % SQL;

    __shared__ float ce[256];
    __shared__ float wsh[48];
    __shared__ float cb[16];
    if (tid < 48) wsh[tid] = conv_w[tid];
    if (tid < 16) cb[tid]  = conv_b[tid];

    for (int idx = tid; idx < 256; idx += 128) {
        int c = idx >> 4, dd = idx & 15;
        int ch = chars[(b*SQL + s)*16 + c];
        ce[idx] = char_emb[ch*16 + dd];
    }
    int w = words[b*SQL + s];
    int row = s*BB + b;
    if (tid < 75) {   // 300 floats = 75 float4
        float4 v = *reinterpret_cast<const float4*>(&word_emb[(size_t)w*300 + tid*4]);
        __nv_bfloat162 lo = __float22bfloat162_rn(make_float2(v.x, v.y));
        __nv_bfloat162 hi = __float22bfloat162_rn(make_float2(v.z, v.w));
        *reinterpret_cast<__nv_bfloat162*>(&X[(size_t)row*LDXP + tid*4])     = lo;
        *reinterpret_cast<__nv_bfloat162*>(&X[(size_t)row*LDXP + tid*4 + 2]) = hi;
    }
    __syncthreads();

    int o = tid >> 3, l = tid & 7;
    float w0 = wsh[o*3], w1 = wsh[o*3+1], w2 = wsh[o*3+2];
    float mx = -1e30f;
    for (int t = l; t < 254; t += 8) {
        float v = ce[t]*w0 + ce[t+1]*w1 + ce[t+2]*w2;
        mx = fmaxf(mx, v);
    }
    #pragma unroll
    for (int off = 4; off; off >>= 1)
        mx = fmaxf(mx, __shfl_down_sync(0xffffffffu, mx, off, 8));
    if (l == 0) {
        float v = mx + cb[o];
        if (b != 0) v = fmaxf(v, 0.f);   // reference quirk: batch row 0 skips relu
        X[(size_t)row*LDXP + 300 + o] = __float2bfloat16(v);
    }
}

// ------------------------- bf16 tensor-core GEMM (cp.async) ----------------
#define SAW 72
#define SA_ELEMS (128*SAW)
#define SB_ELEMS (64*SAW)

__device__ __forceinline__ void mma_bf16(float* c, const uint32_t* a, const uint32_t* b) {
    asm volatile(
        "mma.sync.aligned.m16n8k16.row.col.f32.bf16.bf16.f32 "
        "{%0,%1,%2,%3}, {%4,%5,%6,%7}, {%8,%9}, {%0,%1,%2,%3};"
        : "+f"(c[0]), "+f"(c[1]), "+f"(c[2]), "+f"(c[3])
        : "r"(a[0]), "r"(a[1]), "r"(a[2]), "r"(a[3]), "r"(b[0]), "r"(b[1]));
}
__device__ __forceinline__ void ldsm_x4(uint32_t& r0, uint32_t& r1, uint32_t& r2, uint32_t& r3,
                                        uint32_t addr) {
    asm volatile("ldmatrix.sync.aligned.m8n8.x4.shared.b16 {%0,%1,%2,%3}, [%4];"
        : "=r"(r0), "=r"(r1), "=r"(r2), "=r"(r3) : "r"(addr));
}
__device__ __forceinline__ void cp_async16(uint32_t smem, const void* g, int src_bytes) {
    asm volatile("cp.async.cg.shared.global [%0], [%1], 16, %2;"
        :: "r"(smem), "l"(g), "r"(src_bytes));
}
__device__ __forceinline__ void cp_commit() {
    asm volatile("cp.async.commit_group;");
}
template<int N>
__device__ __forceinline__ void cp_wait() {
    asm volatile("cp.async.wait_group %0;" :: "n"(N));
}

__global__ __launch_bounds__(256, 3) void gemm_wih_bf16(
    const float* __restrict__ bih, const float* __restrict__ bhh, int d, int layer)
{
    const __nv_bfloat16* X = blockIdx.z ? g_HX : g_PX;
    const __nv_bfloat16* Wb = g_W16 + (size_t)layer*400*LDXP;
    float* Y               = blockIdx.z ? g_GH : g_GP;
    extern __shared__ __align__(16) unsigned char smraw[];
    __nv_bfloat16* SA = (__nv_bfloat16*)smraw;        // [2][128*72]
    __nv_bfloat16* SB = SA + 2*SA_ELEMS;              // [2][64*72]
    uint32_t sa_base = (uint32_t)__cvta_generic_to_shared(SA);
    uint32_t sb_base = (uint32_t)__cvta_generic_to_shared(SB);

    int tid  = threadIdx.x;
    int wid  = tid >> 5, lane = tid & 31;
    int wm   = wid >> 1, wn = wid & 1;
    int m0   = blockIdx.y * 128;
    int n0   = blockIdx.x * 64;
    int lg   = lane >> 2;
    int lk   = lane & 3;

    int a_roff = (wm*32 + (lane & 15)) * SAW + ((lane & 16) ? 8 : 0);
    int b_roff = (wn*32 + (lane & 7) + ((lane & 16) ? 8 : 0)) * SAW + ((lane & 8) ? 8 : 0);

    int arow = tid >> 3, ac16 = tid & 7;
    int brow = tid >> 3;

    float acc[2][4][4];
    #pragma unroll
    for (int i = 0; i < 2; i++)
        #pragma unroll
        for (int j = 0; j < 4; j++)
            #pragma unroll
            for (int r = 0; r < 4; r++) acc[i][j][r] = 0.f;

    int nChunk = (d + 63) >> 6;

    auto issueStage = [&](int st, int k0) {
        uint32_t sa = sa_base + st*SA_ELEMS*2;
        uint32_t sb = sb_base + st*SB_ELEMS*2;
        #pragma unroll
        for (int q = 0; q < 4; q++) {
            int row = arow + q*32;
            int c0  = k0 + ac16*8;
            int nb  = (d - c0)*2;
            nb = nb < 0 ? 0 : (nb > 16 ? 16 : nb);
            int cs  = nb ? c0 : 0;
            cp_async16(sa + (row*SAW + ac16*8)*2,
                       &X[(size_t)(m0+row)*LDXP + cs], nb);
        }
        #pragma unroll
        for (int q = 0; q < 2; q++) {
            int row = brow + q*32;
            int nr  = n0 + row;
            int nb  = (nr < 400) ? 16 : 0;
            int rc  = (nr < 400) ? nr : 0;
            int c0  = k0 + ac16*8;
            cp_async16(sb + (row*SAW + ac16*8)*2,
                       &Wb[(size_t)rc*LDXP + c0], nb);
        }
        cp_commit();
    };

    issueStage(0, 0);

    for (int kc = 0; kc < nChunk; kc++) {
        int cur = kc & 1;
        bool more = (kc + 1 < nChunk);
        if (more) issueStage(cur ^ 1, (kc+1) << 6);
        if (more) cp_wait<1>(); else cp_wait<0>();
        __syncthreads();

        uint32_t sa_u = sa_base + cur*SA_ELEMS*2;
        uint32_t sb_u = sb_base + cur*SB_ELEMS*2;
        #pragma unroll
        for (int s = 0; s < 4; s++) {
            uint32_t a[2][4], b[4][2];
            #pragma unroll
            for (int mt = 0; mt < 2; mt++)
                ldsm_x4(a[mt][0], a[mt][1], a[mt][2], a[mt][3],
                        sa_u + 2*(a_roff + mt*16*SAW + s*16));
            #pragma unroll
            for (int ntp = 0; ntp < 2; ntp++) {
                uint32_t r0, r1, r2, r3;
                ldsm_x4(r0, r1, r2, r3, sb_u + 2*(b_roff + ntp*16*SAW + s*16));
                b[2*ntp][0] = r0; b[2*ntp][1] = r1;
                b[2*ntp+1][0] = r2; b[2*ntp+1][1] = r3;
            }
            #pragma unroll
            for (int mt = 0; mt < 2; mt++)
                #pragma unroll
                for (int nt = 0; nt < 4; nt++)
                    mma_bf16(acc[mt][nt], a[mt], b[nt]);
        }
        __syncthreads();
    }

    #pragma unroll
    for (int mt = 0; mt < 2; mt++) {
        int row0 = m0 + wm*32 + mt*16 + lg;
        #pragma unroll
        for (int nt = 0; nt < 4; nt++) {
            int col0 = n0 + wn*32 + nt*8 + 2*lk;
            if (col0 < 400) {
                float bs0 = bih[col0]   + bhh[col0];
                float bs1 = bih[col0+1] + bhh[col0+1];
                Y[(size_t)row0*400 + col0]       = acc[mt][nt][0] + bs0;
                Y[(size_t)row0*400 + col0+1]     = acc[mt][nt][1] + bs1;
                Y[(size_t)(row0+8)*400 + col0]   = acc[mt][nt][2] + bs0;
                Y[(size_t)(row0+8)*400 + col0+1] = acc[mt][nt][3] + bs1;
            }
        }
    }
}

// ------------------------- LSTM recurrence (tanh.approx activations) -------
__device__ __forceinline__ float tanh_ap(float x) {
    float y; asm("tanh.approx.f32 %0, %1;" : "=f"(y) : "f"(x)); return y;
}
__device__ __forceinline__ float sigm_ap(float x) {
    return fmaf(0.5f, tanh_ap(0.5f*x), 0.5f);
}

__global__ __launch_bounds__(512,1) void lstm_kernel(
    const float* __restrict__ whh, int dk, int writeX)
{
    int blk = blockIdx.x;        // 0..127
    int seq = blk >> 6;
    int bp  = blk & 63;
    const float* G = seq ? g_GH : g_GP;
    float* Hout         = seq ? g_HHs : g_PH;
    __nv_bfloat16* Xout = seq ? g_HX  : g_PX;

    int tid  = threadIdx.x;
    int j    = tid % 100;
    int part = tid / 100;        // 0..4 producers; 5 idle tail

    __shared__ __align__(16) float  h_s[2][100];
    __shared__ __align__(16) float4 ps4[2][5][100];

    ull w2[4][10];
    if (part < 5) {
        #pragma unroll
        for (int q = 0; q < 4; q++)
            #pragma unroll
            for (int m = 0; m < 10; m++)
                w2[q][m] = *reinterpret_cast<const ull*>(
                    &whh[(size_t)(q*100 + j)*100 + part*20 + 2*m]);
    }

    int bi = part;               // combiner role for tid<200
    int b  = bi ? bp + 64 : bp;
    float c = 0.f;
    float gr0 = 0.f, gr1 = 0.f, gr2 = 0.f, gr3 = 0.f;
    if (tid < 200) {
        const float* G0 = G + (size_t)b*400;
        gr0 = G0[j]; gr1 = G0[100+j]; gr2 = G0[200+j]; gr3 = G0[300+j];
    }
    if (tid < 100) { h_s[0][tid] = 0.f; h_s[1][tid] = 0.f; }
    __syncthreads();

    for (int t = 0; t < 48; t++) {
        if (part < 5) {
            #pragma unroll
            for (int b2 = 0; b2 < 2; b2++) {
                const ulonglong2* hp = reinterpret_cast<const ulonglong2*>(&h_s[b2][part*20]);
                ull a0 = 0, a1 = 0, a2 = 0, a3 = 0;
                #pragma unroll
                for (int m = 0; m < 5; m++) {
                    ulonglong2 hv = hp[m];
                    fma2(a0, hv.x, w2[0][2*m]);   fma2(a1, hv.x, w2[1][2*m]);
                    fma2(a2, hv.x, w2[2][2*m]);   fma2(a3, hv.x, w2[3][2*m]);
                    fma2(a0, hv.y, w2[0][2*m+1]); fma2(a1, hv.y, w2[1][2*m+1]);
                    fma2(a2, hv.y, w2[2][2*m+1]); fma2(a3, hv.y, w2[3][2*m+1]);
                }
                ps4[b2][part][j] = make_float4(hsum2(a0), hsum2(a1), hsum2(a2), hsum2(a3));
            }
        }
        __syncthreads();
        if (tid < 200) {
            float gi = gr0, gf = gr1, gg = gr2, go = gr3;
            #pragma unroll
            for (int p = 0; p < 5; p++) {
                float4 v = ps4[bi][p][j];
                gi += v.x; gf += v.y; gg += v.z; go += v.w;
            }
            if (t + 1 < 48) {   // prefetch next step's gates
                const float* Gn = G + (size_t)((t+1)*128 + b)*400;
                gr0 = Gn[j]; gr1 = Gn[100+j]; gr2 = Gn[200+j]; gr3 = Gn[300+j];
            }
            c = sigm_ap(gf)*c + sigm_ap(gi)*tanh_ap(gg);
            float h = sigm_ap(go)*tanh_ap(c);
            h_s[bi][j] = h;
            Hout[(size_t)(t*128+b)*100 + j] = h;
            if (writeX)
                Xout[(size_t)(t*128+b)*LDXP + dk + 100 + j] = __float2bfloat16(h);
        }
        __syncthreads();
    }
}

// ------------------------- attn stage 1: scores + softmax E ----------------
__global__ __launch_bounds__(256) void attn_score_kernel()
{
    extern __shared__ __align__(16) float smem[];
    float* hp   = smem;            // 4800
    float* hh   = smem + 4800;     // 4800
    float* attn = smem + 9600;     // 2304
    float* rmax = smem + 11904;    // 48
    float* rinv = rmax + 48;
    float* cmax = rinv + 48;
    float* cinv = cmax + 48;

    int b   = blockIdx.x;
    int tid = threadIdx.x;

    for (int idx = tid; idx < 2400; idx += 256) {
        int s = idx / 50, h2 = (idx % 50)*2;
        *reinterpret_cast<float2*>(&hp[s*100+h2]) =
            *reinterpret_cast<const float2*>(&g_PH [(size_t)(s*128+b)*100 + h2]);
        *reinterpret_cast<float2*>(&hh[s*100+h2]) =
            *reinterpret_cast<const float2*>(&g_HHs[(size_t)(s*128+b)*100 + h2]);
    }
    __syncthreads();

    // score: 3x3 register tile per thread
    {
        int tp = (tid >> 4) * 3;
        int tq = (tid & 15) * 3;
        const ull* hp2 = reinterpret_cast<const ull*>(hp);
        const ull* hh2 = reinterpret_cast<const ull*>(hh);
        ull acc[3][3];
        #pragma unroll
        for (int r = 0; r < 3; r++)
            #pragma unroll
            for (int cc = 0; cc < 3; cc++) acc[r][cc] = 0;
        #pragma unroll 2
        for (int i = 0; i < 50; i++) {
            ull a0 = hp2[(tp  )*50 + i];
            ull a1 = hp2[(tp+1)*50 + i];
            ull a2 = hp2[(tp+2)*50 + i];
            ull b0 = hh2[(tq  )*50 + i];
            ull b1 = hh2[(tq+1)*50 + i];
            ull b2 = hh2[(tq+2)*50 + i];
            fma2(acc[0][0], a0, b0); fma2(acc[0][1], a0, b1); fma2(acc[0][2], a0, b2);
            fma2(acc[1][0], a1, b0); fma2(acc[1][1], a1, b1); fma2(acc[1][2], a1, b2);
            fma2(acc[2][0], a2, b0); fma2(acc[2][1], a2, b1); fma2(acc[2][2], a2, b2);
        }
        #pragma unroll
        for (int r = 0; r < 3; r++)
            #pragma unroll
            for (int cc = 0; cc < 3; cc++)
                attn[(tp+r)*48 + tq+cc] = hsum2(acc[r][cc]);
    }
    __syncthreads();

    if (tid < 192) {
        int line = tid >> 2, sub = tid & 3;
        {   // rows
            float m = -1e30f;
            for (int q = sub; q < 48; q += 4) m = fmaxf(m, attn[line*48+q]);
            m = fmaxf(m, __shfl_xor_sync(0xffffffffu, m, 1, 4));
            m = fmaxf(m, __shfl_xor_sync(0xffffffffu, m, 2, 4));
            float s2 = 0.f;
            for (int q = sub; q < 48; q += 4) s2 += expf(attn[line*48+q]-m);
            s2 += __shfl_xor_sync(0xffffffffu, s2, 1, 4);
            s2 += __shfl_xor_sync(0xffffffffu, s2, 2, 4);
            if (sub == 0) { rmax[line] = m; rinv[line] = 1.f/s2; }
        }
        {   // cols
            float m = -1e30f;
            for (int p = sub; p < 48; p += 4) m = fmaxf(m, attn[p*48+line]);
            m = fmaxf(m, __shfl_xor_sync(0xffffffffu, m, 1, 4));
            m = fmaxf(m, __shfl_xor_sync(0xffffffffu, m, 2, 4));
            float s2 = 0.f;
            for (int p = sub; p < 48; p += 4) s2 += expf(attn[p*48+line]-m);
            s2 += __shfl_xor_sync(0xffffffffu, s2, 1, 4);
            s2 += __shfl_xor_sync(0xffffffffu, s2, 2, 4);
            if (sub == 0) { cmax[line] = m; cinv[line] = 1.f/s2; }
        }
    }
    __syncthreads();

    for (int idx = tid; idx < 2304; idx += 256) {
        int p = idx / 48, q = idx % 48;
        float a = attn[idx];
        g_Erow[(size_t)b*2304 + idx] = expf(a - rmax[p]) * rinv[p];
        g_Ecol[(size_t)b*2304 + idx] = expf(a - cmax[q]) * cinv[q];
    }
}

// ------------------------- attn stage 2: apply (grid 128x2) ----------------
__global__ __launch_bounds__(256) void attn_apply_kernel(int dk)
{
    __shared__ __align__(16) float hv[4800];
    __shared__ __align__(16) float E[2304];

    int b    = blockIdx.x;
    int side = blockIdx.y;     // 0: a_p = Erow @ hh -> g_PX ; 1: a_h = Ecol^T @ hp -> g_HX
    int tid  = threadIdx.x;

    const float* hsrc = side ? g_PH : g_HHs;
    const float* Esrc = (side ? g_Ecol : g_Erow) + (size_t)b*2304;

    for (int idx = tid; idx < 2400; idx += 256) {
        int s = idx / 50, h2 = (idx % 50)*2;
        *reinterpret_cast<float2*>(&hv[s*100+h2]) =
            *reinterpret_cast<const float2*>(&hsrc[(size_t)(s*128+b)*100 + h2]);
    }
    for (int idx = tid; idx < 2304; idx += 256)
        E[idx] = Esrc[idx];
    __syncthreads();

    __nv_bfloat16* Xout = side ? g_HX : g_PX;
    // 600 tiles: (row-pair, float4 col). side 0: rows are p (E[p*48+q] over q);
    // side 1: rows are q (E[p*48+q] over p).
    for (int idx = tid; idx < 600; idx += 256) {
        int rr = idx / 25, c4 = idx % 25;
        int r0 = 2*rr, r1 = 2*rr + 1;
        const ull* hc = reinterpret_cast<const ull*>(hv) + c4*2;
        ull a00 = 0, a01 = 0, a10 = 0, a11 = 0;
        if (side == 0) {
            #pragma unroll 4
            for (int q = 0; q < 48; q++) {
                ull e0 = bcast2(E[r0*48+q]);
                ull e1 = bcast2(E[r1*48+q]);
                ull v0 = hc[q*50], v1 = hc[q*50+1];
                fma2(a00, e0, v0); fma2(a01, e0, v1);
                fma2(a10, e1, v0); fma2(a11, e1, v1);
            }
        } else {
            #pragma unroll 4
            for (int p = 0; p < 48; p++) {
                ull e0 = bcast2(E[p*48+r0]);
                ull e1 = bcast2(E[p*48+r1]);
                ull v0 = hc[p*50], v1 = hc[p*50+1];
                fma2(a00, e0, v0); fma2(a01, e0, v1);
                fma2(a10, e1, v0); fma2(a11, e1, v1);
            }
        }
        float2 r00 = *reinterpret_cast<float2*>(&a00);
        float2 r01 = *reinterpret_cast<float2*>(&a01);
        float2 r10 = *reinterpret_cast<float2*>(&a10);
        float2 r11 = *reinterpret_cast<float2*>(&a11);
        uint2 o0, o1;
        *reinterpret_cast<__nv_bfloat162*>(&o0.x) = __float22bfloat162_rn(r00);
        *reinterpret_cast<__nv_bfloat162*>(&o0.y) = __float22bfloat162_rn(r01);
        *reinterpret_cast<__nv_bfloat162*>(&o1.x) = __float22bfloat162_rn(r10);
        *reinterpret_cast<__nv_bfloat162*>(&o1.y) = __float22bfloat162_rn(r11);
        *reinterpret_cast<uint2*>(&Xout[(size_t)(r0*128+b)*LDXP + dk + 4*c4]) = o0;
        *reinterpret_cast<uint2*>(&Xout[(size_t)(r1*128+b)*LDXP + dk + 4*c4]) = o1;
    }
}

// ------------------------- head: pool -> gemm -> final ---------------------
__global__ __launch_bounds__(128) void pool_kernel()
{
    int b = blockIdx.x, tid = threadIdx.x;
    if (tid < 100) {
        float hq = -1e30f, hs = -1e30f;
        for (int s = 0; s < 48; s++) {
            hq = fmaxf(hq, g_PH [(size_t)(s*128+b)*100 + tid]);
            hs = fmaxf(hs, g_HHs[(size_t)(s*128+b)*100 + tid]);
        }
        g_feats[(tid      )*128 + b] = hq;
        g_feats[(100 + tid)*128 + b] = hs;
        g_feats[(200 + tid)*128 + b] = hs - hq;
        g_feats[(300 + tid)*128 + b] = hq * hs;
        g_feats[(400 + tid)*128 + b] = fabsf(hq - hs);
    }
}

__global__ __launch_bounds__(256) void head_gemm_kernel(
    const float* __restrict__ fcl_w, const float* __restrict__ fcl_b)
{
    __shared__ __align__(16) float fs[50*128];
    __shared__ float ws[8*50];
    int blk = blockIdx.x;       // 0..99
    int o0  = blk * 8;
    int tid = threadIdx.x;
    int ol  = tid >> 5;
    int bb  = tid & 31;

    ull acc[2] = {0, 0};

    for (int kc = 0; kc < 10; kc++) {
        #pragma unroll
        for (int i = 0; i < 25; i++) {
            int idx = tid + 256*i;
            fs[idx] = g_feats[(kc*50)*128 + idx];
        }
        for (int idx = tid; idx < 400; idx += 256) {
            int o = idx / 50, k = idx % 50;
            ws[idx] = fcl_w[(size_t)(o0+o)*500 + kc*50 + k];
        }
        __syncthreads();

        const ull* fs2 = reinterpret_cast<const ull*>(fs);
        #pragma unroll 5
        for (int k = 0; k < 50; k++) {
            ull wv = bcast2(ws[ol*50 + k]);
            fma2(acc[0], wv, fs2[k*64 + bb]);
            fma2(acc[1], wv, fs2[k*64 + bb + 32]);
        }
        __syncthreads();
    }

    float bias = fcl_b[o0 + ol];
    #pragma unroll
    for (int p = 0; p < 2; p++) {
        float2 v = *reinterpret_cast<float2*>(&acc[p]);
        v.x = fmaxf(v.x + bias, 0.f);
        v.y = fmaxf(v.y + bias, 0.f);
        *reinterpret_cast<float2*>(&g_O1[(size_t)(o0+ol)*128 + 2*(bb + 32*p)]) = v;
    }
}

__global__ __launch_bounds__(128) void final_kernel(
    const float* __restrict__ last_w, const float* __restrict__ last_b,
    float* __restrict__ out)
{
    __shared__ float red0[128], red1[128];
    int b = blockIdx.x, tid = threadIdx.x;
    float p0 = 0.f, p1 = 0.f;
    for (int o = tid; o < 800; o += 128) {
        float v = g_O1[(size_t)o*128 + b];
        p0 += v * last_w[o];
        p1 += v * last_w[800 + o];
    }
    red0[tid] = p0; red1[tid] = p1;
    __syncthreads();
    for (int off = 64; off; off >>= 1) {
        if (tid < off) { red0[tid] += red0[tid+off]; red1[tid] += red1[tid+off]; }
        __syncthreads();
    }
    if (tid == 0) {
        out[b*2    ] = 1.f/(1.f+expf(-(red0[0] + last_b[0])));
        out[b*2 + 1] = 1.f/(1.f+expf(-(red1[0] + last_b[1])));
    }
}

// ------------------------- launch ------------------------------------------
extern "C" void kernel_launch(void* const* d_in, const int* in_sizes, int n_in,
                              void* d_out, int out_size)
{
    const int*   q_words  = (const int*)d_in[0];
    const int*   q_chars  = (const int*)d_in[1];
    const int*   s_words  = (const int*)d_in[2];
    const int*   s_chars  = (const int*)d_in[3];
    const float* word_emb = (const float*)d_in[4];
    const float* char_emb = (const float*)d_in[5];
    const float* conv_w   = (const float*)d_in[6];
    const float* conv_b   = (const float*)d_in[7];
    const float* fcl_w    = (const float*)d_in[28];
    const float* fcl_b    = (const float*)d_in[29];
    const float* last_w   = (const float*)d_in[30];
    const float* last_b   = (const float*)d_in[31];
    float* out = (float*)d_out;

    const int gemm_smem  = 2*(SA_ELEMS + SB_ELEMS)*2;   // 55296 bytes
    const int score_smem = 12096*4;                     // 48384 bytes
    cudaFuncSetAttribute(gemm_wih_bf16, cudaFuncAttributeMaxDynamicSharedMemorySize, gemm_smem);
    cudaFuncSetAttribute(attn_score_kernel, cudaFuncAttributeMaxDynamicSharedMemorySize, score_smem);

    // fused: weight conversion (all layers) + embedding, one launch
    prep_kernel<<<14288,128>>>(
        (const float*)d_in[8],  (const float*)d_in[12], (const float*)d_in[16],
        (const float*)d_in[20], (const float*)d_in[24],
        q_words, q_chars, s_words, s_chars,
        word_emb, char_emb, conv_w, conv_b);

    const int dims[5] = {316, 516, 716, 916, 1116};
    for (int k = 0; k < 5; k++) {
        const float* whh = (const float*)d_in[9+4*k];
        const float* bih = (const float*)d_in[10+4*k];
        const float* bhh = (const float*)d_in[11+4*k];
        dim3 gg(7, 48, 2);
        gemm_wih_bf16<<<gg, 256, gemm_smem>>>(bih, bhh, dims[k], k);
        lstm_kernel<<<128, 512>>>(whh, dims[k], (k < 4) ? 1 : 0);
        if (k < 4) {
            attn_score_kernel<<<128, 256, score_smem>>>();
            dim3 ga(128, 2);
            attn_apply_kernel<<<ga, 256>>>(dims[k]);
        }
    }
    pool_kernel<<<128, 128>>>();
    head_gemm_kernel<<<100, 256>>>(fcl_w, fcl_b);
    final_kernel<<<128, 128>>>(last_w, last_b, out);
}

// round 15
// speedup vs baseline: 1.0635x; 1.0635x over previous
#include <cuda_runtime.h>
#include <cuda_bf16.h>
#include <math.h>
#include <stdint.h>

#define SQL 48
#define BB  128
#define HDIM 100
#define LDXP 1120   // padded feature width (bf16 rows, 16B-aligned)

typedef unsigned long long ull;

// ------------------------- scratch (device globals; no allocs) -------------
__device__ __nv_bfloat16 g_PX[SQL*BB*LDXP];    // query features (bf16)
__device__ __nv_bfloat16 g_HX[SQL*BB*LDXP];    // support features
__device__ __nv_bfloat16 g_W16[5*400*LDXP];    // all layers' wih in bf16 (zero-padded)
__device__ float g_GP[SQL*BB*400];             // x@wih^T + biases (query)
__device__ float g_GH[SQL*BB*400];             // (support)
__device__ float g_PH[SQL*BB*HDIM];            // hidden states (query, fp32)
__device__ float g_HHs[SQL*BB*HDIM];           // (support)
__device__ float g_feats[500*128];             // pooled features [k][b]
__device__ float g_O1[800*128];                // fc1 activations [o][b]

__constant__ int c_dims[5] = {316, 516, 716, 916, 1116};

// ------------------------- f32x2 helpers -----------------------------------
__device__ __forceinline__ void fma2(ull &d, ull a, ull b) {
    asm("fma.rn.f32x2 %0, %1, %2, %0;" : "+l"(d) : "l"(a), "l"(b));
}
__device__ __forceinline__ ull bcast2(float x) {
    ull r; asm("mov.b64 %0, {%1, %1};" : "=l"(r) : "f"(x)); return r;
}
__device__ __forceinline__ float hsum2(ull a) {
    float2 v = *reinterpret_cast<float2*>(&a); return v.x + v.y;
}

// ------------------- fused prep: wih->bf16 convert + embedding -------------
__global__ __launch_bounds__(128) void prep_kernel(
    const float* __restrict__ W0, const float* __restrict__ W1,
    const float* __restrict__ W2, const float* __restrict__ W3,
    const float* __restrict__ W4,
    const int* __restrict__ q_words, const int* __restrict__ q_chars,
    const int* __restrict__ s_words, const int* __restrict__ s_chars,
    const float* __restrict__ word_emb, const float* __restrict__ char_emb,
    const float* __restrict__ conv_w, const float* __restrict__ conv_b)
{
    int blk = blockIdx.x;
    int tid = threadIdx.x;

    if (blk < 2000) {   // ---- weight conversion path ----
        int layer = blk / 400;
        int row   = blk % 400;
        const float* Wp[5] = {W0, W1, W2, W3, W4};
        const float* W = Wp[layer];
        int d = c_dims[layer];
        __nv_bfloat16* dst = g_W16 + ((size_t)layer*400 + row)*LDXP;
        for (int c = tid; c < LDXP; c += 128) {
            float v = (c < d) ? W[(size_t)row*d + c] : 0.f;
            dst[c] = __float2bfloat16(v);
        }
        return;
    }

    // ---- embedding path ----
    int e = blk - 2000;             // 0..12287
    int which = e / 6144;
    int m = e % 6144;
    const int* words = which ? s_words : q_words;
    const int* chars = which ? s_chars : q_chars;
    __nv_bfloat16* X = which ? g_HX : g_PX;
    int b = m / SQL;
    int s = m % SQL;

    __shared__ float ce[256];
    __shared__ float wsh[48];
    __shared__ float cb[16];
    if (tid < 48) wsh[tid] = conv_w[tid];
    if (tid < 16) cb[tid]  = conv_b[tid];

    for (int idx = tid; idx < 256; idx += 128) {
        int c = idx >> 4, dd = idx & 15;
        int ch = chars[(b*SQL + s)*16 + c];
        ce[idx] = char_emb[ch*16 + dd];
    }
    int w = words[b*SQL + s];
    int row = s*BB + b;
    if (tid < 75) {   // 300 floats = 75 float4
        float4 v = *reinterpret_cast<const float4*>(&word_emb[(size_t)w*300 + tid*4]);
        __nv_bfloat162 lo = __float22bfloat162_rn(make_float2(v.x, v.y));
        __nv_bfloat162 hi = __float22bfloat162_rn(make_float2(v.z, v.w));
        *reinterpret_cast<__nv_bfloat162*>(&X[(size_t)row*LDXP + tid*4])     = lo;
        *reinterpret_cast<__nv_bfloat162*>(&X[(size_t)row*LDXP + tid*4 + 2]) = hi;
    }
    __syncthreads();

    int o = tid >> 3, l = tid & 7;
    float w0 = wsh[o*3], w1 = wsh[o*3+1], w2 = wsh[o*3+2];
    float mx = -1e30f;
    for (int t = l; t < 254; t += 8) {
        float v = ce[t]*w0 + ce[t+1]*w1 + ce[t+2]*w2;
        mx = fmaxf(mx, v);
    }
    #pragma unroll
    for (int off = 4; off; off >>= 1)
        mx = fmaxf(mx, __shfl_down_sync(0xffffffffu, mx, off, 8));
    if (l == 0) {
        float v = mx + cb[o];
        if (b != 0) v = fmaxf(v, 0.f);   // reference quirk: batch row 0 skips relu
        X[(size_t)row*LDXP + 300 + o] = __float2bfloat16(v);
    }
}

// ------------------------- bf16 tensor-core GEMM (cp.async) ----------------
#define SAW 72
#define SA_ELEMS (128*SAW)
#define SB_ELEMS (64*SAW)

__device__ __forceinline__ void mma_bf16(float* c, const uint32_t* a, const uint32_t* b) {
    asm volatile(
        "mma.sync.aligned.m16n8k16.row.col.f32.bf16.bf16.f32 "
        "{%0,%1,%2,%3}, {%4,%5,%6,%7}, {%8,%9}, {%0,%1,%2,%3};"
        : "+f"(c[0]), "+f"(c[1]), "+f"(c[2]), "+f"(c[3])
        : "r"(a[0]), "r"(a[1]), "r"(a[2]), "r"(a[3]), "r"(b[0]), "r"(b[1]));
}
__device__ __forceinline__ void ldsm_x4(uint32_t& r0, uint32_t& r1, uint32_t& r2, uint32_t& r3,
                                        uint32_t addr) {
    asm volatile("ldmatrix.sync.aligned.m8n8.x4.shared.b16 {%0,%1,%2,%3}, [%4];"
        : "=r"(r0), "=r"(r1), "=r"(r2), "=r"(r3) : "r"(addr));
}
__device__ __forceinline__ void cp_async16(uint32_t smem, const void* g, int src_bytes) {
    asm volatile("cp.async.cg.shared.global [%0], [%1], 16, %2;"
        :: "r"(smem), "l"(g), "r"(src_bytes));
}
__device__ __forceinline__ void cp_commit() {
    asm volatile("cp.async.commit_group;");
}
template<int N>
__device__ __forceinline__ void cp_wait() {
    asm volatile("cp.async.wait_group %0;" :: "n"(N));
}

__global__ __launch_bounds__(256) void gemm_wih_bf16(
    const float* __restrict__ bih, const float* __restrict__ bhh, int d, int layer)
{
    const __nv_bfloat16* X = blockIdx.z ? g_HX : g_PX;
    const __nv_bfloat16* Wb = g_W16 + (size_t)layer*400*LDXP;
    float* Y               = blockIdx.z ? g_GH : g_GP;
    extern __shared__ __align__(16) unsigned char smraw[];
    __nv_bfloat16* SA = (__nv_bfloat16*)smraw;        // [2][128*72]
    __nv_bfloat16* SB = SA + 2*SA_ELEMS;              // [2][64*72]
    uint32_t sa_base = (uint32_t)__cvta_generic_to_shared(SA);
    uint32_t sb_base = (uint32_t)__cvta_generic_to_shared(SB);

    int tid  = threadIdx.x;
    int wid  = tid >> 5, lane = tid & 31;
    int wm   = wid >> 1, wn = wid & 1;
    int m0   = blockIdx.y * 128;
    int n0   = blockIdx.x * 64;
    int lg   = lane >> 2;
    int lk   = lane & 3;

    int a_roff = (wm*32 + (lane & 15)) * SAW + ((lane & 16) ? 8 : 0);
    int b_roff = (wn*32 + (lane & 7) + ((lane & 16) ? 8 : 0)) * SAW + ((lane & 8) ? 8 : 0);

    int arow = tid >> 3, ac16 = tid & 7;
    int brow = tid >> 3;

    float acc[2][4][4];
    #pragma unroll
    for (int i = 0; i < 2; i++)
        #pragma unroll
        for (int j = 0; j < 4; j++)
            #pragma unroll
            for (int r = 0; r < 4; r++) acc[i][j][r] = 0.f;

    int nChunk = (d + 63) >> 6;

    auto issueStage = [&](int st, int k0) {
        uint32_t sa = sa_base + st*SA_ELEMS*2;
        uint32_t sb = sb_base + st*SB_ELEMS*2;
        #pragma unroll
        for (int q = 0; q < 4; q++) {
            int row = arow + q*32;
            int c0  = k0 + ac16*8;
            int nb  = (d - c0)*2;
            nb = nb < 0 ? 0 : (nb > 16 ? 16 : nb);
            int cs  = nb ? c0 : 0;
            cp_async16(sa + (row*SAW + ac16*8)*2,
                       &X[(size_t)(m0+row)*LDXP + cs], nb);
        }
        #pragma unroll
        for (int q = 0; q < 2; q++) {
            int row = brow + q*32;
            int nr  = n0 + row;
            int nb  = (nr < 400) ? 16 : 0;
            int rc  = (nr < 400) ? nr : 0;
            int c0  = k0 + ac16*8;
            cp_async16(sb + (row*SAW + ac16*8)*2,
                       &Wb[(size_t)rc*LDXP + c0], nb);
        }
        cp_commit();
    };

    issueStage(0, 0);

    for (int kc = 0; kc < nChunk; kc++) {
        int cur = kc & 1;
        bool more = (kc + 1 < nChunk);
        if (more) issueStage(cur ^ 1, (kc+1) << 6);
        if (more) cp_wait<1>(); else cp_wait<0>();
        __syncthreads();

        uint32_t sa_u = sa_base + cur*SA_ELEMS*2;
        uint32_t sb_u = sb_base + cur*SB_ELEMS*2;
        #pragma unroll
        for (int s = 0; s < 4; s++) {
            uint32_t a[2][4], b[4][2];
            #pragma unroll
            for (int mt = 0; mt < 2; mt++)
                ldsm_x4(a[mt][0], a[mt][1], a[mt][2], a[mt][3],
                        sa_u + 2*(a_roff + mt*16*SAW + s*16));
            #pragma unroll
            for (int ntp = 0; ntp < 2; ntp++) {
                uint32_t r0, r1, r2, r3;
                ldsm_x4(r0, r1, r2, r3, sb_u + 2*(b_roff + ntp*16*SAW + s*16));
                b[2*ntp][0] = r0; b[2*ntp][1] = r1;
                b[2*ntp+1][0] = r2; b[2*ntp+1][1] = r3;
            }
            #pragma unroll
            for (int mt = 0; mt < 2; mt++)
                #pragma unroll
                for (int nt = 0; nt < 4; nt++)
                    mma_bf16(acc[mt][nt], a[mt], b[nt]);
        }
        __syncthreads();
    }

    #pragma unroll
    for (int mt = 0; mt < 2; mt++) {
        int row0 = m0 + wm*32 + mt*16 + lg;
        #pragma unroll
        for (int nt = 0; nt < 4; nt++) {
            int col0 = n0 + wn*32 + nt*8 + 2*lk;
            if (col0 < 400) {
                float bs0 = bih[col0]   + bhh[col0];
                float bs1 = bih[col0+1] + bhh[col0+1];
                Y[(size_t)row0*400 + col0]       = acc[mt][nt][0] + bs0;
                Y[(size_t)row0*400 + col0+1]     = acc[mt][nt][1] + bs1;
                Y[(size_t)(row0+8)*400 + col0]   = acc[mt][nt][2] + bs0;
                Y[(size_t)(row0+8)*400 + col0+1] = acc[mt][nt][3] + bs1;
            }
        }
    }
}

// ------------------------- LSTM recurrence (tanh.approx activations) -------
__device__ __forceinline__ float tanh_ap(float x) {
    float y; asm("tanh.approx.f32 %0, %1;" : "=f"(y) : "f"(x)); return y;
}
__device__ __forceinline__ float sigm_ap(float x) {
    return fmaf(0.5f, tanh_ap(0.5f*x), 0.5f);
}

__global__ __launch_bounds__(512,1) void lstm_kernel(
    const float* __restrict__ whh, int dk, int writeX)
{
    int blk = blockIdx.x;        // 0..127
    int seq = blk >> 6;
    int bp  = blk & 63;
    const float* G = seq ? g_GH : g_GP;
    float* Hout         = seq ? g_HHs : g_PH;
    __nv_bfloat16* Xout = seq ? g_HX  : g_PX;

    int tid  = threadIdx.x;
    int j    = tid % 100;
    int part = tid / 100;        // 0..4 producers; 5 idle tail

    __shared__ __align__(16) float  h_s[2][100];
    __shared__ __align__(16) float4 ps4[2][5][100];

    ull w2[4][10];
    if (part < 5) {
        #pragma unroll
        for (int q = 0; q < 4; q++)
            #pragma unroll
            for (int m = 0; m < 10; m++)
                w2[q][m] = *reinterpret_cast<const ull*>(
                    &whh[(size_t)(q*100 + j)*100 + part*20 + 2*m]);
    }

    int bi = part;               // combiner role for tid<200
    int b  = bi ? bp + 64 : bp;
    float c = 0.f;
    float gr0 = 0.f, gr1 = 0.f, gr2 = 0.f, gr3 = 0.f;
    if (tid < 200) {
        const float* G0 = G + (size_t)b*400;
        gr0 = G0[j]; gr1 = G0[100+j]; gr2 = G0[200+j]; gr3 = G0[300+j];
    }
    if (tid < 100) { h_s[0][tid] = 0.f; h_s[1][tid] = 0.f; }
    __syncthreads();

    for (int t = 0; t < 48; t++) {
        if (part < 5) {
            #pragma unroll
            for (int b2 = 0; b2 < 2; b2++) {
                const ulonglong2* hp = reinterpret_cast<const ulonglong2*>(&h_s[b2][part*20]);
                ull a0 = 0, a1 = 0, a2 = 0, a3 = 0;
                #pragma unroll
                for (int m = 0; m < 5; m++) {
                    ulonglong2 hv = hp[m];
                    fma2(a0, hv.x, w2[0][2*m]);   fma2(a1, hv.x, w2[1][2*m]);
                    fma2(a2, hv.x, w2[2][2*m]);   fma2(a3, hv.x, w2[3][2*m]);
                    fma2(a0, hv.y, w2[0][2*m+1]); fma2(a1, hv.y, w2[1][2*m+1]);
                    fma2(a2, hv.y, w2[2][2*m+1]); fma2(a3, hv.y, w2[3][2*m+1]);
                }
                ps4[b2][part][j] = make_float4(hsum2(a0), hsum2(a1), hsum2(a2), hsum2(a3));
            }
        }
        __syncthreads();
        if (tid < 200) {
            float gi = gr0, gf = gr1, gg = gr2, go = gr3;
            #pragma unroll
            for (int p = 0; p < 5; p++) {
                float4 v = ps4[bi][p][j];
                gi += v.x; gf += v.y; gg += v.z; go += v.w;
            }
            if (t + 1 < 48) {   // prefetch next step's gates
                const float* Gn = G + (size_t)((t+1)*128 + b)*400;
                gr0 = Gn[j]; gr1 = Gn[100+j]; gr2 = Gn[200+j]; gr3 = Gn[300+j];
            }
            c = sigm_ap(gf)*c + sigm_ap(gi)*tanh_ap(gg);
            float h = sigm_ap(go)*tanh_ap(c);
            h_s[bi][j] = h;
            Hout[(size_t)(t*128+b)*100 + j] = h;
            if (writeX)
                Xout[(size_t)(t*128+b)*LDXP + dk + 100 + j] = __float2bfloat16(h);
        }
        __syncthreads();
    }
}

// ------------------------- cross attention (256 thr, register-tiled) -------
// Single kernel (measured best). One pass computes BOTH softmax E matrices:
// E (row-softmax) into its own buffer, col-softmax overwrites attn in place.
__global__ __launch_bounds__(256) void attn_kernel(int dk)
{
    extern __shared__ __align__(16) float smem[];
    float* hp   = smem;            // 4800
    float* hh   = smem + 4800;     // 4800
    float* attn = smem + 9600;     // 2304 (raw scores -> col-softmax E in place)
    float* E    = smem + 11904;    // 2304 (row-softmax E)
    float* rmax = smem + 14208;    // 48
    float* rinv = rmax + 48;       // 48
    float* cmax = rinv + 48;       // 48
    float* cinv = cmax + 48;       // 48

    int b   = blockIdx.x;
    int tid = threadIdx.x;

    for (int idx = tid; idx < 2400; idx += 256) {
        int s = idx / 50, h2 = (idx % 50)*2;
        *reinterpret_cast<float2*>(&hp[s*100+h2]) =
            *reinterpret_cast<const float2*>(&g_PH [(size_t)(s*128+b)*100 + h2]);
        *reinterpret_cast<float2*>(&hh[s*100+h2]) =
            *reinterpret_cast<const float2*>(&g_HHs[(size_t)(s*128+b)*100 + h2]);
    }
    __syncthreads();

    // score: 3x3 register tile per thread (16x16 tile grid)
    {
        int tp = (tid >> 4) * 3;
        int tq = (tid & 15) * 3;
        const ull* hp2 = reinterpret_cast<const ull*>(hp);
        const ull* hh2 = reinterpret_cast<const ull*>(hh);
        ull acc[3][3];
        #pragma unroll
        for (int r = 0; r < 3; r++)
            #pragma unroll
            for (int cc = 0; cc < 3; cc++) acc[r][cc] = 0;
        #pragma unroll 2
        for (int i = 0; i < 50; i++) {
            ull a0 = hp2[(tp  )*50 + i];
            ull a1 = hp2[(tp+1)*50 + i];
            ull a2 = hp2[(tp+2)*50 + i];
            ull b0 = hh2[(tq  )*50 + i];
            ull b1 = hh2[(tq+1)*50 + i];
            ull b2 = hh2[(tq+2)*50 + i];
            fma2(acc[0][0], a0, b0); fma2(acc[0][1], a0, b1); fma2(acc[0][2], a0, b2);
            fma2(acc[1][0], a1, b0); fma2(acc[1][1], a1, b1); fma2(acc[1][2], a1, b2);
            fma2(acc[2][0], a2, b0); fma2(acc[2][1], a2, b1); fma2(acc[2][2], a2, b2);
        }
        #pragma unroll
        for (int r = 0; r < 3; r++)
            #pragma unroll
            for (int cc = 0; cc < 3; cc++)
                attn[(tp+r)*48 + tq+cc] = hsum2(acc[r][cc]);
    }
    __syncthreads();

    // softmax stats, rows then cols (quad-parallel: 48 lines x 4 threads)
    if (tid < 192) {
        int line = tid >> 2, sub = tid & 3;
        {   // rows
            float m = -1e30f;
            for (int q = sub; q < 48; q += 4) m = fmaxf(m, attn[line*48+q]);
            m = fmaxf(m, __shfl_xor_sync(0xffffffffu, m, 1, 4));
            m = fmaxf(m, __shfl_xor_sync(0xffffffffu, m, 2, 4));
            float s2 = 0.f;
            for (int q = sub; q < 48; q += 4) s2 += expf(attn[line*48+q]-m);
            s2 += __shfl_xor_sync(0xffffffffu, s2, 1, 4);
            s2 += __shfl_xor_sync(0xffffffffu, s2, 2, 4);
            if (sub == 0) { rmax[line] = m; rinv[line] = 1.f/s2; }
        }
        {   // cols
            float m = -1e30f;
            for (int p = sub; p < 48; p += 4) m = fmaxf(m, attn[p*48+line]);
            m = fmaxf(m, __shfl_xor_sync(0xffffffffu, m, 1, 4));
            m = fmaxf(m, __shfl_xor_sync(0xffffffffu, m, 2, 4));
            float s2 = 0.f;
            for (int p = sub; p < 48; p += 4) s2 += expf(attn[p*48+line]-m);
            s2 += __shfl_xor_sync(0xffffffffu, s2, 1, 4);
            s2 += __shfl_xor_sync(0xffffffffu, s2, 2, 4);
            if (sub == 0) { cmax[line] = m; cinv[line] = 1.f/s2; }
        }
    }
    __syncthreads();

    // ONE pass: E = row softmax; attn <- col softmax (in place)
    for (int idx = tid; idx < 2304; idx += 256) {
        int p = idx / 48, q = idx % 48;
        float a = attn[idx];
        E[idx]    = expf(a - rmax[p]) * rinv[p];
        attn[idx] = expf(a - cmax[q]) * cinv[q];
    }
    __syncthreads();

    // a_p = E(rows) @ hh -> g_PX ; 600 tiles: (p-pair, float4 col)
    for (int idx = tid; idx < 600; idx += 256) {
        int pp = idx / 25, c4 = idx % 25;
        int p0 = 2*pp, p1 = 2*pp + 1;
        const ull* hc = reinterpret_cast<const ull*>(hh) + c4*2;
        ull a00 = 0, a01 = 0, a10 = 0, a11 = 0;
        #pragma unroll 4
        for (int q = 0; q < 48; q++) {
            ull e0 = bcast2(E[p0*48+q]);
            ull e1 = bcast2(E[p1*48+q]);
            ull v0 = hc[q*50], v1 = hc[q*50+1];
            fma2(a00, e0, v0); fma2(a01, e0, v1);
            fma2(a10, e1, v0); fma2(a11, e1, v1);
        }
        float2 r00 = *reinterpret_cast<float2*>(&a00);
        float2 r01 = *reinterpret_cast<float2*>(&a01);
        float2 r10 = *reinterpret_cast<float2*>(&a10);
        float2 r11 = *reinterpret_cast<float2*>(&a11);
        uint2 o0, o1;
        *reinterpret_cast<__nv_bfloat162*>(&o0.x) = __float22bfloat162_rn(r00);
        *reinterpret_cast<__nv_bfloat162*>(&o0.y) = __float22bfloat162_rn(r01);
        *reinterpret_cast<__nv_bfloat162*>(&o1.x) = __float22bfloat162_rn(r10);
        *reinterpret_cast<__nv_bfloat162*>(&o1.y) = __float22bfloat162_rn(r11);
        *reinterpret_cast<uint2*>(&g_PX[(size_t)(p0*128+b)*LDXP + dk + 4*c4]) = o0;
        *reinterpret_cast<uint2*>(&g_PX[(size_t)(p1*128+b)*LDXP + dk + 4*c4]) = o1;
    }

    // a_h = attn(col softmax)^T @ hp -> g_HX (no barrier needed: attn final)
    for (int idx = tid; idx < 600; idx += 256) {
        int qq = idx / 25, c4 = idx % 25;
        int q0 = 2*qq, q1 = 2*qq + 1;
        const ull* hc = reinterpret_cast<const ull*>(hp) + c4*2;
        ull a00 = 0, a01 = 0, a10 = 0, a11 = 0;
        #pragma unroll 4
        for (int p = 0; p < 48; p++) {
            ull e0 = bcast2(attn[p*48+q0]);
            ull e1 = bcast2(attn[p*48+q1]);
            ull v0 = hc[p*50], v1 = hc[p*50+1];
            fma2(a00, e0, v0); fma2(a01, e0, v1);
            fma2(a10, e1, v0); fma2(a11, e1, v1);
        }
        float2 r00 = *reinterpret_cast<float2*>(&a00);
        float2 r01 = *reinterpret_cast<float2*>(&a01);
        float2 r10 = *reinterpret_cast<float2*>(&a10);
        float2 r11 = *reinterpret_cast<float2*>(&a11);
        uint2 o0, o1;
        *reinterpret_cast<__nv_bfloat162*>(&o0.x) = __float22bfloat162_rn(r00);
        *reinterpret_cast<__nv_bfloat162*>(&o0.y) = __float22bfloat162_rn(r01);
        *reinterpret_cast<__nv_bfloat162*>(&o1.x) = __float22bfloat162_rn(r10);
        *reinterpret_cast<__nv_bfloat162*>(&o1.y) = __float22bfloat162_rn(r11);
        *reinterpret_cast<uint2*>(&g_HX[(size_t)(q0*128+b)*LDXP + dk + 4*c4]) = o0;
        *reinterpret_cast<uint2*>(&g_HX[(size_t)(q1*128+b)*LDXP + dk + 4*c4]) = o1;
    }
}

// ------------------------- head: pool -> gemm -> final ---------------------
__global__ __launch_bounds__(128) void pool_kernel()
{
    int b = blockIdx.x, tid = threadIdx.x;
    if (tid < 100) {
        float hq = -1e30f, hs = -1e30f;
        for (int s = 0; s < 48; s++) {
            hq = fmaxf(hq, g_PH [(size_t)(s*128+b)*100 + tid]);
            hs = fmaxf(hs, g_HHs[(size_t)(s*128+b)*100 + tid]);
        }
        g_feats[(tid      )*128 + b] = hq;
        g_feats[(100 + tid)*128 + b] = hs;
        g_feats[(200 + tid)*128 + b] = hs - hq;
        g_feats[(300 + tid)*128 + b] = hq * hs;
        g_feats[(400 + tid)*128 + b] = fabsf(hq - hs);
    }
}

__global__ __launch_bounds__(256) void head_gemm_kernel(
    const float* __restrict__ fcl_w, const float* __restrict__ fcl_b)
{
    __shared__ __align__(16) float fs[50*128];
    __shared__ float ws[8*50];
    int blk = blockIdx.x;       // 0..99
    int o0  = blk * 8;
    int tid = threadIdx.x;
    int ol  = tid >> 5;
    int bb  = tid & 31;

    ull acc[2] = {0, 0};

    for (int kc = 0; kc < 10; kc++) {
        #pragma unroll
        for (int i = 0; i < 25; i++) {
            int idx = tid + 256*i;
            fs[idx] = g_feats[(kc*50)*128 + idx];
        }
        for (int idx = tid; idx < 400; idx += 256) {
            int o = idx / 50, k = idx % 50;
            ws[idx] = fcl_w[(size_t)(o0+o)*500 + kc*50 + k];
        }
        __syncthreads();

        const ull* fs2 = reinterpret_cast<const ull*>(fs);
        #pragma unroll 5
        for (int k = 0; k < 50; k++) {
            ull wv = bcast2(ws[ol*50 + k]);
            fma2(acc[0], wv, fs2[k*64 + bb]);
            fma2(acc[1], wv, fs2[k*64 + bb + 32]);
        }
        __syncthreads();
    }

    float bias = fcl_b[o0 + ol];
    #pragma unroll
    for (int p = 0; p < 2; p++) {
        float2 v = *reinterpret_cast<float2*>(&acc[p]);
        v.x = fmaxf(v.x + bias, 0.f);
        v.y = fmaxf(v.y + bias, 0.f);
        *reinterpret_cast<float2*>(&g_O1[(size_t)(o0+ol)*128 + 2*(bb + 32*p)]) = v;
    }
}

__global__ __launch_bounds__(128) void final_kernel(
    const float* __restrict__ last_w, const float* __restrict__ last_b,
    float* __restrict__ out)
{
    __shared__ float red0[128], red1[128];
    int b = blockIdx.x, tid = threadIdx.x;
    float p0 = 0.f, p1 = 0.f;
    for (int o = tid; o < 800; o += 128) {
        float v = g_O1[(size_t)o*128 + b];
        p0 += v * last_w[o];
        p1 += v * last_w[800 + o];
    }
    red0[tid] = p0; red1[tid] = p1;
    __syncthreads();
    for (int off = 64; off; off >>= 1) {
        if (tid < off) { red0[tid] += red0[tid+off]; red1[tid] += red1[tid+off]; }
        __syncthreads();
    }
    if (tid == 0) {
        out[b*2    ] = 1.f/(1.f+expf(-(red0[0] + last_b[0])));
        out[b*2 + 1] = 1.f/(1.f+expf(-(red1[0] + last_b[1])));
    }
}

// ------------------------- launch ------------------------------------------
extern "C" void kernel_launch(void* const* d_in, const int* in_sizes, int n_in,
                              void* d_out, int out_size)
{
    const int*   q_words  = (const int*)d_in[0];
    const int*   q_chars  = (const int*)d_in[1];
    const int*   s_words  = (const int*)d_in[2];
    const int*   s_chars  = (const int*)d_in[3];
    const float* word_emb = (const float*)d_in[4];
    const float* char_emb = (const float*)d_in[5];
    const float* conv_w   = (const float*)d_in[6];
    const float* conv_b   = (const float*)d_in[7];
    const float* fcl_w    = (const float*)d_in[28];
    const float* fcl_b    = (const float*)d_in[29];
    const float* last_w   = (const float*)d_in[30];
    const float* last_b   = (const float*)d_in[31];
    float* out = (float*)d_out;

    const int gemm_smem = 2*(SA_ELEMS + SB_ELEMS)*2;   // 55296 bytes
    const int attn_smem = 14400*4;                     // 57600 bytes
    cudaFuncSetAttribute(gemm_wih_bf16, cudaFuncAttributeMaxDynamicSharedMemorySize, gemm_smem);
    cudaFuncSetAttribute(attn_kernel, cudaFuncAttributeMaxDynamicSharedMemorySize, attn_smem);

    // fused: weight conversion (all layers) + embedding, one launch
    prep_kernel<<<14288,128>>>(
        (const float*)d_in[8],  (const float*)d_in[12], (const float*)d_in[16],
        (const float*)d_in[20], (const float*)d_in[24],
        q_words, q_chars, s_words, s_chars,
        word_emb, char_emb, conv_w, conv_b);

    const int dims[5] = {316, 516, 716, 916, 1116};
    for (int k = 0; k < 5; k++) {
        const float* whh = (const float*)d_in[9+4*k];
        const float* bih = (const float*)d_in[10+4*k];
        const float* bhh = (const float*)d_in[11+4*k];
        dim3 gg(7, 48, 2);
        gemm_wih_bf16<<<gg, 256, gemm_smem>>>(bih, bhh, dims[k], k);
        lstm_kernel<<<128, 512>>>(whh, dims[k], (k < 4) ? 1 : 0);
        if (k < 4) attn_kernel<<<128, 256, attn_smem>>>(dims[k]);
    }
    pool_kernel<<<128, 128>>>();
    head_gemm_kernel<<<100, 256>>>(fcl_w, fcl_b);
    final_kernel<<<128, 128>>>(last_w, last_b, out);
}

// round 16
// speedup vs baseline: 1.0883x; 1.0233x over previous
#include <cuda_runtime.h>
#include <cuda_bf16.h>
#include <math.h>
#include <stdint.h>

#define SQL 48
#define BB  128
#define HDIM 100
#define LDXP 1120   // padded feature width (bf16 rows, 16B-aligned)

typedef unsigned long long ull;

// ------------------------- scratch (device globals; no allocs) -------------
__device__ __nv_bfloat16 g_PX[SQL*BB*LDXP];    // query features (bf16)
__device__ __nv_bfloat16 g_HX[SQL*BB*LDXP];    // support features
__device__ __nv_bfloat16 g_W16[5*400*LDXP];    // all layers' wih in bf16 (zero-padded)
__device__ float g_GP[SQL*BB*400];             // x@wih^T + biases (query)
__device__ float g_GH[SQL*BB*400];             // (support)
__device__ float g_PH[SQL*BB*HDIM];            // hidden states (query, fp32)
__device__ float g_HHs[SQL*BB*HDIM];           // (support)
__device__ float g_feats[500*128];             // pooled features [k][b]
__device__ float g_O1[800*128];                // fc1 activations [o][b]

__constant__ int c_dims[5] = {316, 516, 716, 916, 1116};

// ------------------------- f32x2 helpers -----------------------------------
__device__ __forceinline__ void fma2(ull &d, ull a, ull b) {
    asm("fma.rn.f32x2 %0, %1, %2, %0;" : "+l"(d) : "l"(a), "l"(b));
}
__device__ __forceinline__ ull bcast2(float x) {
    ull r; asm("mov.b64 %0, {%1, %1};" : "=l"(r) : "f"(x)); return r;
}
__device__ __forceinline__ float hsum2(ull a) {
    float2 v = *reinterpret_cast<float2*>(&a); return v.x + v.y;
}

// ------------------- fused prep: wih->bf16 convert + embedding -------------
__global__ __launch_bounds__(128) void prep_kernel(
    const float* __restrict__ W0, const float* __restrict__ W1,
    const float* __restrict__ W2, const float* __restrict__ W3,
    const float* __restrict__ W4,
    const int* __restrict__ q_words, const int* __restrict__ q_chars,
    const int* __restrict__ s_words, const int* __restrict__ s_chars,
    const float* __restrict__ word_emb, const float* __restrict__ char_emb,
    const float* __restrict__ conv_w, const float* __restrict__ conv_b)
{
    cudaGridDependencySynchronize();
    int blk = blockIdx.x;
    int tid = threadIdx.x;

    if (blk < 2000) {   // ---- weight conversion path ----
        int layer = blk / 400;
        int row   = blk % 400;
        const float* Wp[5] = {W0, W1, W2, W3, W4};
        const float* W = Wp[layer];
        int d = c_dims[layer];
        __nv_bfloat16* dst = g_W16 + ((size_t)layer*400 + row)*LDXP;
        for (int c = tid; c < LDXP; c += 128) {
            float v = (c < d) ? W[(size_t)row*d + c] : 0.f;
            dst[c] = __float2bfloat16(v);
        }
        return;
    }

    // ---- embedding path ----
    int e = blk - 2000;             // 0..12287
    int which = e / 6144;
    int m = e % 6144;
    const int* words = which ? s_words : q_words;
    const int* chars = which ? s_chars : q_chars;
    __nv_bfloat16* X = which ? g_HX : g_PX;
    int b = m / SQL;
    int s = m % SQL;

    __shared__ float ce[256];
    __shared__ float wsh[48];
    __shared__ float cb[16];
    if (tid < 48) wsh[tid] = conv_w[tid];
    if (tid < 16) cb[tid]  = conv_b[tid];

    for (int idx = tid; idx < 256; idx += 128) {
        int c = idx >> 4, dd = idx & 15;
        int ch = chars[(b*SQL + s)*16 + c];
        ce[idx] = char_emb[ch*16 + dd];
    }
    int w = words[b*SQL + s];
    int row = s*BB + b;
    if (tid < 75) {   // 300 floats = 75 float4
        float4 v = *reinterpret_cast<const float4*>(&word_emb[(size_t)w*300 + tid*4]);
        __nv_bfloat162 lo = __float22bfloat162_rn(make_float2(v.x, v.y));
        __nv_bfloat162 hi = __float22bfloat162_rn(make_float2(v.z, v.w));
        *reinterpret_cast<__nv_bfloat162*>(&X[(size_t)row*LDXP + tid*4])     = lo;
        *reinterpret_cast<__nv_bfloat162*>(&X[(size_t)row*LDXP + tid*4 + 2]) = hi;
    }
    __syncthreads();

    int o = tid >> 3, l = tid & 7;
    float w0 = wsh[o*3], w1 = wsh[o*3+1], w2 = wsh[o*3+2];
    float mx = -1e30f;
    for (int t = l; t < 254; t += 8) {
        float v = ce[t]*w0 + ce[t+1]*w1 + ce[t+2]*w2;
        mx = fmaxf(mx, v);
    }
    #pragma unroll
    for (int off = 4; off; off >>= 1)
        mx = fmaxf(mx, __shfl_down_sync(0xffffffffu, mx, off, 8));
    if (l == 0) {
        float v = mx + cb[o];
        if (b != 0) v = fmaxf(v, 0.f);   // reference quirk: batch row 0 skips relu
        X[(size_t)row*LDXP + 300 + o] = __float2bfloat16(v);
    }
}

// ------------------------- bf16 tensor-core GEMM (cp.async) ----------------
#define SAW 72
#define SA_ELEMS (128*SAW)
#define SB_ELEMS (64*SAW)

__device__ __forceinline__ void mma_bf16(float* c, const uint32_t* a, const uint32_t* b) {
    asm volatile(
        "mma.sync.aligned.m16n8k16.row.col.f32.bf16.bf16.f32 "
        "{%0,%1,%2,%3}, {%4,%5,%6,%7}, {%8,%9}, {%0,%1,%2,%3};"
        : "+f"(c[0]), "+f"(c[1]), "+f"(c[2]), "+f"(c[3])
        : "r"(a[0]), "r"(a[1]), "r"(a[2]), "r"(a[3]), "r"(b[0]), "r"(b[1]));
}
__device__ __forceinline__ void ldsm_x4(uint32_t& r0, uint32_t& r1, uint32_t& r2, uint32_t& r3,
                                        uint32_t addr) {
    asm volatile("ldmatrix.sync.aligned.m8n8.x4.shared.b16 {%0,%1,%2,%3}, [%4];"
        : "=r"(r0), "=r"(r1), "=r"(r2), "=r"(r3) : "r"(addr));
}
__device__ __forceinline__ void cp_async16(uint32_t smem, const void* g, int src_bytes) {
    asm volatile("cp.async.cg.shared.global [%0], [%1], 16, %2;"
        :: "r"(smem), "l"(g), "r"(src_bytes));
}
__device__ __forceinline__ void cp_commit() {
    asm volatile("cp.async.commit_group;");
}
template<int N>
__device__ __forceinline__ void cp_wait() {
    asm volatile("cp.async.wait_group %0;" :: "n"(N));
}

__global__ __launch_bounds__(256) void gemm_wih_bf16(
    const float* __restrict__ bih, const float* __restrict__ bhh, int d, int layer)
{
    const __nv_bfloat16* X = blockIdx.z ? g_HX : g_PX;
    const __nv_bfloat16* Wb = g_W16 + (size_t)layer*400*LDXP;
    float* Y               = blockIdx.z ? g_GH : g_GP;
    extern __shared__ __align__(16) unsigned char smraw[];
    __nv_bfloat16* SA = (__nv_bfloat16*)smraw;        // [2][128*72]
    __nv_bfloat16* SB = SA + 2*SA_ELEMS;              // [2][64*72]
    uint32_t sa_base = (uint32_t)__cvta_generic_to_shared(SA);
    uint32_t sb_base = (uint32_t)__cvta_generic_to_shared(SB);

    int tid  = threadIdx.x;
    int wid  = tid >> 5, lane = tid & 31;
    int wm   = wid >> 1, wn = wid & 1;
    int m0   = blockIdx.y * 128;
    int n0   = blockIdx.x * 64;
    int lg   = lane >> 2;
    int lk   = lane & 3;

    int a_roff = (wm*32 + (lane & 15)) * SAW + ((lane & 16) ? 8 : 0);
    int b_roff = (wn*32 + (lane & 7) + ((lane & 16) ? 8 : 0)) * SAW + ((lane & 8) ? 8 : 0);

    int arow = tid >> 3, ac16 = tid & 7;
    int brow = tid >> 3;

    float acc[2][4][4];
    #pragma unroll
    for (int i = 0; i < 2; i++)
        #pragma unroll
        for (int j = 0; j < 4; j++)
            #pragma unroll
            for (int r = 0; r < 4; r++) acc[i][j][r] = 0.f;

    int nChunk = (d + 63) >> 6;

    auto issueStage = [&](int st, int k0) {
        uint32_t sa = sa_base + st*SA_ELEMS*2;
        uint32_t sb = sb_base + st*SB_ELEMS*2;
        #pragma unroll
        for (int q = 0; q < 4; q++) {
            int row = arow + q*32;
            int c0  = k0 + ac16*8;
            int nb  = (d - c0)*2;
            nb = nb < 0 ? 0 : (nb > 16 ? 16 : nb);
            int cs  = nb ? c0 : 0;
            cp_async16(sa + (row*SAW + ac16*8)*2,
                       &X[(size_t)(m0+row)*LDXP + cs], nb);
        }
        #pragma unroll
        for (int q = 0; q < 2; q++) {
            int row = brow + q*32;
            int nr  = n0 + row;
            int nb  = (nr < 400) ? 16 : 0;
            int rc  = (nr < 400) ? nr : 0;
            int c0  = k0 + ac16*8;
            cp_async16(sb + (row*SAW + ac16*8)*2,
                       &Wb[(size_t)rc*LDXP + c0], nb);
        }
        cp_commit();
    };

    cudaGridDependencySynchronize();
    issueStage(0, 0);

    for (int kc = 0; kc < nChunk; kc++) {
        int cur = kc & 1;
        bool more = (kc + 1 < nChunk);
        if (more) issueStage(cur ^ 1, (kc+1) << 6);
        if (more) cp_wait<1>(); else cp_wait<0>();
        __syncthreads();

        uint32_t sa_u = sa_base + cur*SA_ELEMS*2;
        uint32_t sb_u = sb_base + cur*SB_ELEMS*2;
        #pragma unroll
        for (int s = 0; s < 4; s++) {
            uint32_t a[2][4], b[4][2];
            #pragma unroll
            for (int mt = 0; mt < 2; mt++)
                ldsm_x4(a[mt][0], a[mt][1], a[mt][2], a[mt][3],
                        sa_u + 2*(a_roff + mt*16*SAW + s*16));
            #pragma unroll
            for (int ntp = 0; ntp < 2; ntp++) {
                uint32_t r0, r1, r2, r3;
                ldsm_x4(r0, r1, r2, r3, sb_u + 2*(b_roff + ntp*16*SAW + s*16));
                b[2*ntp][0] = r0; b[2*ntp][1] = r1;
                b[2*ntp+1][0] = r2; b[2*ntp+1][1] = r3;
            }
            #pragma unroll
            for (int mt = 0; mt < 2; mt++)
                #pragma unroll
                for (int nt = 0; nt < 4; nt++)
                    mma_bf16(acc[mt][nt], a[mt], b[nt]);
        }
        __syncthreads();
    }

    #pragma unroll
    for (int mt = 0; mt < 2; mt++) {
        int row0 = m0 + wm*32 + mt*16 + lg;
        #pragma unroll
        for (int nt = 0; nt < 4; nt++) {
            int col0 = n0 + wn*32 + nt*8 + 2*lk;
            if (col0 < 400) {
                float bs0 = bih[col0]   + bhh[col0];
                float bs1 = bih[col0+1] + bhh[col0+1];
                Y[(size_t)row0*400 + col0]       = acc[mt][nt][0] + bs0;
                Y[(size_t)row0*400 + col0+1]     = acc[mt][nt][1] + bs1;
                Y[(size_t)(row0+8)*400 + col0]   = acc[mt][nt][2] + bs0;
                Y[(size_t)(row0+8)*400 + col0+1] = acc[mt][nt][3] + bs1;
            }
        }
    }
}

// ------------------------- LSTM recurrence (tanh.approx activations) -------
// writeX moved to attn (h columns are written there from its smem copies).
__device__ __forceinline__ float tanh_ap(float x) {
    float y; asm("tanh.approx.f32 %0, %1;" : "=f"(y) : "f"(x)); return y;
}
__device__ __forceinline__ float sigm_ap(float x) {
    return fmaf(0.5f, tanh_ap(0.5f*x), 0.5f);
}

__global__ __launch_bounds__(512,1) void lstm_kernel(const float* __restrict__ whh)
{
    int blk = blockIdx.x;        // 0..127
    int seq = blk >> 6;
    int bp  = blk & 63;
    const float* G = seq ? g_GH : g_GP;
    float* Hout    = seq ? g_HHs : g_PH;

    int tid  = threadIdx.x;
    int j    = tid % 100;
    int part = tid / 100;        // 0..4 producers; 5 idle tail

    __shared__ __align__(16) float  h_s[2][100];
    __shared__ __align__(16) float4 ps4[2][5][100];

    cudaGridDependencySynchronize();

    ull w2[4][10];
    if (part < 5) {
        #pragma unroll
        for (int q = 0; q < 4; q++)
            #pragma unroll
            for (int m = 0; m < 10; m++)
                w2[q][m] = *reinterpret_cast<const ull*>(
                    &whh[(size_t)(q*100 + j)*100 + part*20 + 2*m]);
    }

    int bi = part;               // combiner role for tid<200
    int b  = bi ? bp + 64 : bp;
    float c = 0.f;
    float gr0 = 0.f, gr1 = 0.f, gr2 = 0.f, gr3 = 0.f;
    if (tid < 200) {
        const float* G0 = G + (size_t)b*400;
        gr0 = G0[j]; gr1 = G0[100+j]; gr2 = G0[200+j]; gr3 = G0[300+j];
    }
    if (tid < 100) { h_s[0][tid] = 0.f; h_s[1][tid] = 0.f; }
    __syncthreads();

    for (int t = 0; t < 48; t++) {
        if (part < 5) {
            #pragma unroll
            for (int b2 = 0; b2 < 2; b2++) {
                const ulonglong2* hp = reinterpret_cast<const ulonglong2*>(&h_s[b2][part*20]);
                ull a0 = 0, a1 = 0, a2 = 0, a3 = 0;
                #pragma unroll
                for (int m = 0; m < 5; m++) {
                    ulonglong2 hv = hp[m];
                    fma2(a0, hv.x, w2[0][2*m]);   fma2(a1, hv.x, w2[1][2*m]);
                    fma2(a2, hv.x, w2[2][2*m]);   fma2(a3, hv.x, w2[3][2*m]);
                    fma2(a0, hv.y, w2[0][2*m+1]); fma2(a1, hv.y, w2[1][2*m+1]);
                    fma2(a2, hv.y, w2[2][2*m+1]); fma2(a3, hv.y, w2[3][2*m+1]);
                }
                ps4[b2][part][j] = make_float4(hsum2(a0), hsum2(a1), hsum2(a2), hsum2(a3));
            }
        }
        __syncthreads();
        if (tid < 200) {
            float gi = gr0, gf = gr1, gg = gr2, go = gr3;
            #pragma unroll
            for (int p = 0; p < 5; p++) {
                float4 v = ps4[bi][p][j];
                gi += v.x; gf += v.y; gg += v.z; go += v.w;
            }
            if (t + 1 < 48) {   // prefetch next step's gates
                const float* Gn = G + (size_t)((t+1)*128 + b)*400;
                gr0 = Gn[j]; gr1 = Gn[100+j]; gr2 = Gn[200+j]; gr3 = Gn[300+j];
            }
            c = sigm_ap(gf)*c + sigm_ap(gi)*tanh_ap(gg);
            float h = sigm_ap(go)*tanh_ap(c);
            h_s[bi][j] = h;
            Hout[(size_t)(t*128+b)*100 + j] = h;
        }
        __syncthreads();
    }
}

// ------------------------- cross attention (256 thr, register-tiled) -------
// Also writes the h columns into X (moved out of lstm's serial loop).
__global__ __launch_bounds__(256) void attn_kernel(int dk)
{
    extern __shared__ __align__(16) float smem[];
    float* hp   = smem;            // 4800
    float* hh   = smem + 4800;     // 4800
    float* attn = smem + 9600;     // 2304 (raw scores -> col-softmax E in place)
    float* E    = smem + 11904;    // 2304 (row-softmax E)
    float* rmax = smem + 14208;    // 48
    float* rinv = rmax + 48;       // 48
    float* cmax = rinv + 48;       // 48
    float* cinv = cmax + 48;       // 48

    int b   = blockIdx.x;
    int tid = threadIdx.x;

    cudaGridDependencySynchronize();

    for (int idx = tid; idx < 2400; idx += 256) {
        int s = idx / 50, h2 = (idx % 50)*2;
        *reinterpret_cast<float2*>(&hp[s*100+h2]) =
            *reinterpret_cast<const float2*>(&g_PH [(size_t)(s*128+b)*100 + h2]);
        *reinterpret_cast<float2*>(&hh[s*100+h2]) =
            *reinterpret_cast<const float2*>(&g_HHs[(size_t)(s*128+b)*100 + h2]);
    }
    __syncthreads();

    // write h columns into X (cols [dk+100, dk+200)) from smem copies
    for (int idx = tid; idx < 1200; idx += 256) {
        int s = idx / 25, pr = idx % 25;
        float2 vp = *reinterpret_cast<const float2*>(&hp[s*100 + 2*pr]);
        float2 vh = *reinterpret_cast<const float2*>(&hh[s*100 + 2*pr]);
        *reinterpret_cast<__nv_bfloat162*>(&g_PX[(size_t)(s*128+b)*LDXP + dk + 100 + 2*pr]) =
            __float22bfloat162_rn(vp);
        *reinterpret_cast<__nv_bfloat162*>(&g_HX[(size_t)(s*128+b)*LDXP + dk + 100 + 2*pr]) =
            __float22bfloat162_rn(vh);
    }

    // score: 3x3 register tile per thread (16x16 tile grid)
    {
        int tp = (tid >> 4) * 3;
        int tq = (tid & 15) * 3;
        const ull* hp2 = reinterpret_cast<const ull*>(hp);
        const ull* hh2 = reinterpret_cast<const ull*>(hh);
        ull acc[3][3];
        #pragma unroll
        for (int r = 0; r < 3; r++)
            #pragma unroll
            for (int cc = 0; cc < 3; cc++) acc[r][cc] = 0;
        #pragma unroll 2
        for (int i = 0; i < 50; i++) {
            ull a0 = hp2[(tp  )*50 + i];
            ull a1 = hp2[(tp+1)*50 + i];
            ull a2 = hp2[(tp+2)*50 + i];
            ull b0 = hh2[(tq  )*50 + i];
            ull b1 = hh2[(tq+1)*50 + i];
            ull b2 = hh2[(tq+2)*50 + i];
            fma2(acc[0][0], a0, b0); fma2(acc[0][1], a0, b1); fma2(acc[0][2], a0, b2);
            fma2(acc[1][0], a1, b0); fma2(acc[1][1], a1, b1); fma2(acc[1][2], a1, b2);
            fma2(acc[2][0], a2, b0); fma2(acc[2][1], a2, b1); fma2(acc[2][2], a2, b2);
        }
        #pragma unroll
        for (int r = 0; r < 3; r++)
            #pragma unroll
            for (int cc = 0; cc < 3; cc++)
                attn[(tp+r)*48 + tq+cc] = hsum2(acc[r][cc]);
    }
    __syncthreads();

    // softmax stats, rows then cols (quad-parallel: 48 lines x 4 threads)
    if (tid < 192) {
        int line = tid >> 2, sub = tid & 3;
        {   // rows
            float m = -1e30f;
            for (int q = sub; q < 48; q += 4) m = fmaxf(m, attn[line*48+q]);
            m = fmaxf(m, __shfl_xor_sync(0xffffffffu, m, 1, 4));
            m = fmaxf(m, __shfl_xor_sync(0xffffffffu, m, 2, 4));
            float s2 = 0.f;
            for (int q = sub; q < 48; q += 4) s2 += expf(attn[line*48+q]-m);
            s2 += __shfl_xor_sync(0xffffffffu, s2, 1, 4);
            s2 += __shfl_xor_sync(0xffffffffu, s2, 2, 4);
            if (sub == 0) { rmax[line] = m; rinv[line] = 1.f/s2; }
        }
        {   // cols
            float m = -1e30f;
            for (int p = sub; p < 48; p += 4) m = fmaxf(m, attn[p*48+line]);
            m = fmaxf(m, __shfl_xor_sync(0xffffffffu, m, 1, 4));
            m = fmaxf(m, __shfl_xor_sync(0xffffffffu, m, 2, 4));
            float s2 = 0.f;
            for (int p = sub; p < 48; p += 4) s2 += expf(attn[p*48+line]-m);
            s2 += __shfl_xor_sync(0xffffffffu, s2, 1, 4);
            s2 += __shfl_xor_sync(0xffffffffu, s2, 2, 4);
            if (sub == 0) { cmax[line] = m; cinv[line] = 1.f/s2; }
        }
    }
    __syncthreads();

    // ONE pass: E = row softmax; attn <- col softmax (in place)
    for (int idx = tid; idx < 2304; idx += 256) {
        int p = idx / 48, q = idx % 48;
        float a = attn[idx];
        E[idx]    = expf(a - rmax[p]) * rinv[p];
        attn[idx] = expf(a - cmax[q]) * cinv[q];
    }
    __syncthreads();

    // a_p = E(rows) @ hh -> g_PX ; 600 tiles: (p-pair, float4 col)
    for (int idx = tid; idx < 600; idx += 256) {
        int pp = idx / 25, c4 = idx % 25;
        int p0 = 2*pp, p1 = 2*pp + 1;
        const ull* hc = reinterpret_cast<const ull*>(hh) + c4*2;
        ull a00 = 0, a01 = 0, a10 = 0, a11 = 0;
        #pragma unroll 4
        for (int q = 0; q < 48; q++) {
            ull e0 = bcast2(E[p0*48+q]);
            ull e1 = bcast2(E[p1*48+q]);
            ull v0 = hc[q*50], v1 = hc[q*50+1];
            fma2(a00, e0, v0); fma2(a01, e0, v1);
            fma2(a10, e1, v0); fma2(a11, e1, v1);
        }
        float2 r00 = *reinterpret_cast<float2*>(&a00);
        float2 r01 = *reinterpret_cast<float2*>(&a01);
        float2 r10 = *reinterpret_cast<float2*>(&a10);
        float2 r11 = *reinterpret_cast<float2*>(&a11);
        uint2 o0, o1;
        *reinterpret_cast<__nv_bfloat162*>(&o0.x) = __float22bfloat162_rn(r00);
        *reinterpret_cast<__nv_bfloat162*>(&o0.y) = __float22bfloat162_rn(r01);
        *reinterpret_cast<__nv_bfloat162*>(&o1.x) = __float22bfloat162_rn(r10);
        *reinterpret_cast<__nv_bfloat162*>(&o1.y) = __float22bfloat162_rn(r11);
        *reinterpret_cast<uint2*>(&g_PX[(size_t)(p0*128+b)*LDXP + dk + 4*c4]) = o0;
        *reinterpret_cast<uint2*>(&g_PX[(size_t)(p1*128+b)*LDXP + dk + 4*c4]) = o1;
    }

    // a_h = attn(col softmax)^T @ hp -> g_HX (no barrier needed: attn final)
    for (int idx = tid; idx < 600; idx += 256) {
        int qq = idx / 25, c4 = idx % 25;
        int q0 = 2*qq, q1 = 2*qq + 1;
        const ull* hc = reinterpret_cast<const ull*>(hp) + c4*2;
        ull a00 = 0, a01 = 0, a10 = 0, a11 = 0;
        #pragma unroll 4
        for (int p = 0; p < 48; p++) {
            ull e0 = bcast2(attn[p*48+q0]);
            ull e1 = bcast2(attn[p*48+q1]);
            ull v0 = hc[p*50], v1 = hc[p*50+1];
            fma2(a00, e0, v0); fma2(a01, e0, v1);
            fma2(a10, e1, v0); fma2(a11, e1, v1);
        }
        float2 r00 = *reinterpret_cast<float2*>(&a00);
        float2 r01 = *reinterpret_cast<float2*>(&a01);
        float2 r10 = *reinterpret_cast<float2*>(&a10);
        float2 r11 = *reinterpret_cast<float2*>(&a11);
        uint2 o0, o1;
        *reinterpret_cast<__nv_bfloat162*>(&o0.x) = __float22bfloat162_rn(r00);
        *reinterpret_cast<__nv_bfloat162*>(&o0.y) = __float22bfloat162_rn(r01);
        *reinterpret_cast<__nv_bfloat162*>(&o1.x) = __float22bfloat162_rn(r10);
        *reinterpret_cast<__nv_bfloat162*>(&o1.y) = __float22bfloat162_rn(r11);
        *reinterpret_cast<uint2*>(&g_HX[(size_t)(q0*128+b)*LDXP + dk + 4*c4]) = o0;
        *reinterpret_cast<uint2*>(&g_HX[(size_t)(q1*128+b)*LDXP + dk + 4*c4]) = o1;
    }
}

// ------------------------- head: pool -> gemm -> final ---------------------
__global__ __launch_bounds__(128) void pool_kernel()
{
    cudaGridDependencySynchronize();
    int b = blockIdx.x, tid = threadIdx.x;
    if (tid < 100) {
        float hq = -1e30f, hs = -1e30f;
        for (int s = 0; s < 48; s++) {
            hq = fmaxf(hq, g_PH [(size_t)(s*128+b)*100 + tid]);
            hs = fmaxf(hs, g_HHs[(size_t)(s*128+b)*100 + tid]);
        }
        g_feats[(tid      )*128 + b] = hq;
        g_feats[(100 + tid)*128 + b] = hs;
        g_feats[(200 + tid)*128 + b] = hs - hq;
        g_feats[(300 + tid)*128 + b] = hq * hs;
        g_feats[(400 + tid)*128 + b] = fabsf(hq - hs);
    }
}

__global__ __launch_bounds__(256) void head_gemm_kernel(
    const float* __restrict__ fcl_w, const float* __restrict__ fcl_b)
{
    __shared__ __align__(16) float fs[50*128];
    __shared__ float ws[8*50];
    int blk = blockIdx.x;       // 0..99
    int o0  = blk * 8;
    int tid = threadIdx.x;
    int ol  = tid >> 5;
    int bb  = tid & 31;

    cudaGridDependencySynchronize();

    ull acc[2] = {0, 0};

    for (int kc = 0; kc < 10; kc++) {
        #pragma unroll
        for (int i = 0; i < 25; i++) {
            int idx = tid + 256*i;
            fs[idx] = g_feats[(kc*50)*128 + idx];
        }
        for (int idx = tid; idx < 400; idx += 256) {
            int o = idx / 50, k = idx % 50;
            ws[idx] = fcl_w[(size_t)(o0+o)*500 + kc*50 + k];
        }
        __syncthreads();

        const ull* fs2 = reinterpret_cast<const ull*>(fs);
        #pragma unroll 5
        for (int k = 0; k < 50; k++) {
            ull wv = bcast2(ws[ol*50 + k]);
            fma2(acc[0], wv, fs2[k*64 + bb]);
            fma2(acc[1], wv, fs2[k*64 + bb + 32]);
        }
        __syncthreads();
    }

    float bias = fcl_b[o0 + ol];
    #pragma unroll
    for (int p = 0; p < 2; p++) {
        float2 v = *reinterpret_cast<float2*>(&acc[p]);
        v.x = fmaxf(v.x + bias, 0.f);
        v.y = fmaxf(v.y + bias, 0.f);
        *reinterpret_cast<float2*>(&g_O1[(size_t)(o0+ol)*128 + 2*(bb + 32*p)]) = v;
    }
}

__global__ __launch_bounds__(128) void final_kernel(
    const float* __restrict__ last_w, const float* __restrict__ last_b,
    float* __restrict__ out)
{
    __shared__ float red0[128], red1[128];
    int b = blockIdx.x, tid = threadIdx.x;
    cudaGridDependencySynchronize();
    float p0 = 0.f, p1 = 0.f;
    for (int o = tid; o < 800; o += 128) {
        float v = g_O1[(size_t)o*128 + b];
        p0 += v * last_w[o];
        p1 += v * last_w[800 + o];
    }
    red0[tid] = p0; red1[tid] = p1;
    __syncthreads();
    for (int off = 64; off; off >>= 1) {
        if (tid < off) { red0[tid] += red0[tid+off]; red1[tid] += red1[tid+off]; }
        __syncthreads();
    }
    if (tid == 0) {
        out[b*2    ] = 1.f/(1.f+expf(-(red0[0] + last_b[0])));
        out[b*2 + 1] = 1.f/(1.f+expf(-(red1[0] + last_b[1])));
    }
}

// ------------------------- launch helpers (PDL) -----------------------------
template <typename F, typename... Args>
static inline void launch_pdl(F kernel, dim3 grid, dim3 block, size_t smem, Args... args)
{
    cudaLaunchConfig_t cfg = {};
    cfg.gridDim = grid;
    cfg.blockDim = block;
    cfg.dynamicSmemBytes = smem;
    cfg.stream = 0;
    cudaLaunchAttribute at[1];
    at[0].id = cudaLaunchAttributeProgrammaticStreamSerialization;
    at[0].val.programmaticStreamSerializationAllowed = 1;
    cfg.attrs = at;
    cfg.numAttrs = 1;
    cudaLaunchKernelEx(&cfg, kernel, args...);
}

// ------------------------- launch ------------------------------------------
extern "C" void kernel_launch(void* const* d_in, const int* in_sizes, int n_in,
                              void* d_out, int out_size)
{
    const int*   q_words  = (const int*)d_in[0];
    const int*   q_chars  = (const int*)d_in[1];
    const int*   s_words  = (const int*)d_in[2];
    const int*   s_chars  = (const int*)d_in[3];
    const float* word_emb = (const float*)d_in[4];
    const float* char_emb = (const float*)d_in[5];
    const float* conv_w   = (const float*)d_in[6];
    const float* conv_b   = (const float*)d_in[7];
    const float* fcl_w    = (const float*)d_in[28];
    const float* fcl_b    = (const float*)d_in[29];
    const float* last_w   = (const float*)d_in[30];
    const float* last_b   = (const float*)d_in[31];
    float* out = (float*)d_out;

    const int gemm_smem = 2*(SA_ELEMS + SB_ELEMS)*2;   // 55296 bytes
    const int attn_smem = 14400*4;                     // 57600 bytes
    cudaFuncSetAttribute(gemm_wih_bf16, cudaFuncAttributeMaxDynamicSharedMemorySize, gemm_smem);
    cudaFuncSetAttribute(attn_kernel, cudaFuncAttributeMaxDynamicSharedMemorySize, attn_smem);

    launch_pdl(prep_kernel, dim3(14288), dim3(128), 0,
        (const float*)d_in[8],  (const float*)d_in[12], (const float*)d_in[16],
        (const float*)d_in[20], (const float*)d_in[24],
        q_words, q_chars, s_words, s_chars,
        word_emb, char_emb, conv_w, conv_b);

    const int dims[5] = {316, 516, 716, 916, 1116};
    for (int k = 0; k < 5; k++) {
        const float* whh = (const float*)d_in[9+4*k];
        const float* bih = (const float*)d_in[10+4*k];
        const float* bhh = (const float*)d_in[11+4*k];
        launch_pdl(gemm_wih_bf16, dim3(7, 48, 2), dim3(256), (size_t)gemm_smem,
                   bih, bhh, dims[k], k);
        launch_pdl(lstm_kernel, dim3(128), dim3(512), 0, whh);
        if (k < 4)
            launch_pdl(attn_kernel, dim3(128), dim3(256), (size_t)attn_smem, dims[k]);
    }
    launch_pdl(pool_kernel, dim3(128), dim3(128), 0);
    launch_pdl(head_gemm_kernel, dim3(100), dim3(256), 0, fcl_w, fcl_b);
    launch_pdl(final_kernel, dim3(128), dim3(128), 0, last_w, last_b, out);
}